// round 10
// baseline (speedup 1.0000x reference)
#include <cuda_runtime.h>
#include <cuda_bf16.h>
#include <mma.h>
#include <math.h>

using namespace nvcuda;

// ---------------- problem constants ----------------
#define BB   16
#define SS   512
#define DD   768
#define HH   12
#define DNN  64
#define FF   3072
#define LL   6
#define MT   (BB*SS)        // 8192 tokens
#define NQKV (3*DD)         // 2304
#define BH   (BB*HH)        // 192
#define NEGB (-1e9f)

// ---------------- scratch (device globals: allocation-free rule) ----------------
__device__ float g_h[MT*DD];                       //  25 MB
__device__ float g_qkv[MT*NQKV];                   //  75 MB
__device__ float g_attn[MT*DD];                    //  25 MB
__device__ float g_proj[MT*DD];                    //  25 MB
__device__ float g_ffn[MT*FF];                     // 100 MB
__device__ float g_scores[(size_t)BH*SS*SS];       // 201 MB
__device__ float g_wqkv[(size_t)LL*DD*NQKV];       //  42 MB
__device__ float g_pe[SS*DD];

// ---------------- small reductions ----------------
__device__ __forceinline__ float warp_sum(float v){
    #pragma unroll
    for (int o=16;o;o>>=1) v += __shfl_xor_sync(0xffffffffu, v, o);
    return v;
}
__device__ __forceinline__ float warp_max(float v){
    #pragma unroll
    for (int o=16;o;o>>=1) v = fmaxf(v, __shfl_xor_sync(0xffffffffu, v, o));
    return v;
}
__device__ __forceinline__ float block_sum8(float v, float* red){
    v = warp_sum(v);
    if ((threadIdx.x & 31) == 0) red[threadIdx.x >> 5] = v;
    __syncthreads();
    float t = red[0];
    #pragma unroll
    for (int i=1;i<8;i++) t += red[i];
    __syncthreads();
    return t;
}
__device__ __forceinline__ float block_max8(float v, float* red){
    v = warp_max(v);
    if ((threadIdx.x & 31) == 0) red[threadIdx.x >> 5] = v;
    __syncthreads();
    float t = red[0];
    #pragma unroll
    for (int i=1;i<8;i++) t = fmaxf(t, red[i]);
    __syncthreads();
    return t;
}

// ---------------- positional encoding table (double math, exact enough) ----------------
__global__ void pe_kernel(float* __restrict__ pe){
    int idx = blockIdx.x*256 + threadIdx.x;
    if (idx >= SS*DD) return;
    int pos = idx / DD, c = idx % DD;
    double i = (double)(c >> 1);
    float val;
    if ((c & 1) == 0) {
        double ang = (double)pos * pow(10000.0, -2.0*i/(double)DD);
        val = (float)sin(ang);
    } else {
        double ang = (double)pos * pow(10000.0, -2.0*(i+1.0)/(double)DD);
        val = (float)cos(ang);
    }
    pe[idx] = val;
}

// ---------------- embedding + PE ----------------
__global__ void embed_kernel(const int* __restrict__ x, const float* __restrict__ emb,
                             const float* __restrict__ pe, float* __restrict__ h){
    long long idx = (long long)blockIdx.x*256 + threadIdx.x;
    if (idx >= (long long)MT*DD) return;
    int m = (int)(idx / DD), c = (int)(idx % DD);
    int tok = x[m];
    h[idx] = emb[(long long)tok*DD + c] + pe[(m & (SS-1))*DD + c];
}

// ---------------- pack per-head QKV weights into row-major [L][D][2304] ----------------
__global__ void pack_wqkv_kernel(const float* __restrict__ Wq, const float* __restrict__ Wk,
                                 const float* __restrict__ Wv, float* __restrict__ out){
    long long i = (long long)blockIdx.x*256 + threadIdx.x;
    const long long TOT = (long long)LL*DD*NQKV;
    if (i >= TOT) return;
    int n = (int)(i % NQKV);
    long long t = i / NQKV;
    int d = (int)(t % DD);
    int l = (int)(t / DD);
    int seg = n / DD, nn = n % DD;
    int hh = nn >> 6, e = nn & 63;
    const float* W = (seg==0) ? Wq : (seg==1 ? Wk : Wv);
    out[i] = W[(((long long)l*HH + hh)*DD + d)*DNN + e];
}

// ---------------- generic strided bf16x3 tensor-core GEMM ----------------
// C[M,N] = A[M,K] * B[K,N], fp32 in/out, bf16 hi/lo split (3 MMAs) for ~fp32 accuracy.
// bmode: 0 plain; 1 attention scores (batch z=b*12+h over qkv->scores);
//        2 attn*V (batch z over scores,qkv->attn_out)
#define TM 128
#define TN 128
#define TK 32
#define ALD 48
#define BLD 144

__global__ void __launch_bounds__(256) gemm_bf16x3_kernel(
    const float* __restrict__ A, long long sAm, long long sAk,
    const float* __restrict__ B, long long sBk, long long sBn,
    float* __restrict__ C, int ldc,
    int M, int N, int K, int bmode)
{
    __shared__ alignas(32) __nv_bfloat16 Ah[TM][ALD];
    __shared__ alignas(32) __nv_bfloat16 Al[TM][ALD];
    __shared__ alignas(32) __nv_bfloat16 Bh[TK][BLD];
    __shared__ alignas(32) __nv_bfloat16 Bl[TK][BLD];

    int z = blockIdx.z;
    if (bmode == 1) {            // scores: Q[s,e] * K[t,e]^T
        int b = z / HH, hh = z % HH;
        A += (long long)b*SS*NQKV + (long long)hh*DNN;          // q block
        B += (long long)b*SS*NQKV + DD + (long long)hh*DNN;     // k block
        C += (long long)z*SS*SS;
    } else if (bmode == 2) {     // attn[s,t] * V[t,e]
        int b = z / HH, hh = z % HH;
        A += (long long)z*SS*SS;
        B += (long long)b*SS*NQKV + 2*DD + (long long)hh*DNN;   // v block
        C += (long long)b*SS*DD + (long long)hh*DNN;
    }

    const int tid  = threadIdx.x;
    const int warp = tid >> 5;
    const int wr   = warp >> 2;   // 0..1
    const int wc   = warp & 3;    // 0..3
    const int row0 = blockIdx.y * TM;
    const int col0 = blockIdx.x * TN;
    const bool b_ncontig = (sBn == 1);

    wmma::fragment<wmma::accumulator,16,16,16,float> acc[4][2];
    #pragma unroll
    for (int i=0;i<4;i++)
        #pragma unroll
        for (int j=0;j<2;j++) wmma::fill_fragment(acc[i][j], 0.0f);

    for (int k0 = 0; k0 < K; k0 += TK) {
        // ---- stage A tile (128 x 32), split to hi/lo bf16 ----
        #pragma unroll
        for (int it=0; it<(TM*TK)/256; it++) {
            int i = tid + it*256;
            int r = i >> 5, c = i & 31;   // k contiguous in all our A layouts
            float v = A[(long long)(row0 + r)*sAm + (long long)(k0 + c)*sAk];
            __nv_bfloat16 hi = __float2bfloat16(v);
            float rem = v - __bfloat162float(hi);
            Ah[r][c] = hi;
            Al[r][c] = __float2bfloat16(rem);
        }
        // ---- stage B tile (32 x 128) ----
        #pragma unroll
        for (int it=0; it<(TK*TN)/256; it++) {
            int i = tid + it*256;
            int r, c;
            if (b_ncontig) { r = i >> 7; c = i & 127; }
            else           { c = i >> 5; r = i & 31; }   // k-contiguous source (Q.K^T)
            int gn = col0 + c;
            float v = (gn < N) ? B[(long long)(k0 + r)*sBk + (long long)gn*sBn] : 0.0f;
            __nv_bfloat16 hi = __float2bfloat16(v);
            float rem = v - __bfloat162float(hi);
            Bh[r][c] = hi;
            Bl[r][c] = __float2bfloat16(rem);
        }
        __syncthreads();

        #pragma unroll
        for (int kk=0; kk<TK; kk+=16) {
            wmma::fragment<wmma::matrix_b,16,16,16,__nv_bfloat16,wmma::row_major> fbh[2], fbl[2];
            #pragma unroll
            for (int j=0;j<2;j++) {
                wmma::load_matrix_sync(fbh[j], &Bh[kk][wc*32 + j*16], BLD);
                wmma::load_matrix_sync(fbl[j], &Bl[kk][wc*32 + j*16], BLD);
            }
            #pragma unroll
            for (int i=0;i<4;i++) {
                wmma::fragment<wmma::matrix_a,16,16,16,__nv_bfloat16,wmma::row_major> fah, fal;
                wmma::load_matrix_sync(fah, &Ah[wr*64 + i*16][kk], ALD);
                wmma::load_matrix_sync(fal, &Al[wr*64 + i*16][kk], ALD);
                #pragma unroll
                for (int j=0;j<2;j++) {
                    wmma::mma_sync(acc[i][j], fah, fbh[j], acc[i][j]);
                    wmma::mma_sync(acc[i][j], fal, fbh[j], acc[i][j]);
                    wmma::mma_sync(acc[i][j], fah, fbl[j], acc[i][j]);
                }
            }
        }
        __syncthreads();
    }

    // ---- store ----
    #pragma unroll
    for (int i=0;i<4;i++) {
        int r = row0 + wr*64 + i*16;
        #pragma unroll
        for (int j=0;j<2;j++) {
            int c = col0 + wc*32 + j*16;
            if (c < N)
                wmma::store_matrix_sync(C + (long long)r*ldc + c, acc[i][j], ldc, wmma::mem_row_major);
        }
    }
}

// ---------------- epilogues ----------------
__global__ void bias_qkv_kernel(float* __restrict__ qkv, const float* __restrict__ bq,
                                const float* __restrict__ bk, const float* __restrict__ bv, int l){
    long long i = (long long)blockIdx.x*256 + threadIdx.x;
    if (i >= (long long)MT*NQKV) return;
    int n = (int)(i % NQKV);
    const float* bb = (n < DD) ? bq : (n < 2*DD ? bk : bv);
    qkv[i] += bb[l*DD + (n % DD)];
}

__global__ void bias_relu_kernel(float* __restrict__ t, const float* __restrict__ b1, int l){
    long long i = (long long)blockIdx.x*256 + threadIdx.x;
    if (i >= (long long)MT*FF) return;
    int n = (int)(i % FF);
    float v = t[i] + b1[(long long)l*FF + n];
    t[i] = fmaxf(v, 0.0f);
}

// scale + mask-bias + softmax over each score row of 512
__global__ void __launch_bounds__(256) softmax_kernel(float* __restrict__ scores,
                                                      const int* __restrict__ mask){
    __shared__ float red[8];
    long long r = blockIdx.x;                 // [0, 192*512)
    long long z = r >> 9;                     // b*12 + h
    int s = (int)(r & (SS-1));
    int b = (int)(z / HH);
    float* Srow = scores + r*SS;
    const int* Mrow = mask + ((long long)b*SS + s)*SS;
    int tid = threadIdx.x;

    int t0 = tid, t1 = tid + 256;
    float v0 = Srow[t0]*0.125f + (Mrow[t0] ? NEGB : 0.0f);
    float v1 = Srow[t1]*0.125f + (Mrow[t1] ? NEGB : 0.0f);
    float mx = block_max8(fmaxf(v0, v1), red);
    float e0 = expf(v0 - mx), e1 = expf(v1 - mx);
    float sum = block_sum8(e0 + e1, red);
    float inv = 1.0f / sum;
    Srow[t0] = e0 * inv;
    Srow[t1] = e1 * inv;
}

// out = LayerNorm(hin + proj + bias) * gamma + beta   (row = token, 768 wide)
__global__ void __launch_bounds__(256) resid_ln_kernel(
    const float* __restrict__ hin, const float* __restrict__ proj,
    const float* __restrict__ bias, const float* __restrict__ gamma,
    const float* __restrict__ beta, float* __restrict__ hout)
{
    __shared__ float red[8];
    long long row = blockIdx.x;
    int tid = threadIdx.x;
    float v[3];
    float s = 0.0f;
    #pragma unroll
    for (int t=0;t<3;t++){
        int c = tid + t*256;
        float val = hin[row*DD + c] + proj[row*DD + c] + bias[c];
        v[t] = val; s += val;
    }
    s = block_sum8(s, red);
    float mean = s * (1.0f/DD);
    float sq = 0.0f;
    #pragma unroll
    for (int t=0;t<3;t++){ float d = v[t]-mean; sq += d*d; }
    sq = block_sum8(sq, red);
    float rstd = rsqrtf(sq*(1.0f/DD) + 1e-5f);
    #pragma unroll
    for (int t=0;t<3;t++){
        int c = tid + t*256;
        hout[row*DD + c] = (v[t]-mean)*rstd*gamma[c] + beta[c];
    }
}

// ---------------- host orchestration ----------------
extern "C" void kernel_launch(void* const* d_in, const int* in_sizes, int n_in,
                              void* d_out, int out_size)
{
    (void)in_sizes; (void)n_in; (void)out_size;
    const int*   x    = (const int*)  d_in[0];
    const int*   mask = (const int*)  d_in[1];
    const float* emb  = (const float*)d_in[2];
    const float* Wq   = (const float*)d_in[3];
    const float* bq   = (const float*)d_in[4];
    const float* Wk   = (const float*)d_in[5];
    const float* bk   = (const float*)d_in[6];
    const float* Wv   = (const float*)d_in[7];
    const float* bv   = (const float*)d_in[8];
    const float* Wo   = (const float*)d_in[9];
    const float* bo   = (const float*)d_in[10];
    const float* W1   = (const float*)d_in[11];
    const float* b1   = (const float*)d_in[12];
    const float* W2   = (const float*)d_in[13];
    const float* b2   = (const float*)d_in[14];
    const float* g1   = (const float*)d_in[15];
    const float* be1  = (const float*)d_in[16];
    const float* g2   = (const float*)d_in[17];
    const float* be2  = (const float*)d_in[18];
    float* out = (float*)d_out;

    float *h, *qkv, *attn, *proj, *ffn, *scores, *wqkv, *pe;
    cudaGetSymbolAddress((void**)&h,      g_h);
    cudaGetSymbolAddress((void**)&qkv,    g_qkv);
    cudaGetSymbolAddress((void**)&attn,   g_attn);
    cudaGetSymbolAddress((void**)&proj,   g_proj);
    cudaGetSymbolAddress((void**)&ffn,    g_ffn);
    cudaGetSymbolAddress((void**)&scores, g_scores);
    cudaGetSymbolAddress((void**)&wqkv,   g_wqkv);
    cudaGetSymbolAddress((void**)&pe,     g_pe);

    pe_kernel<<<(SS*DD + 255)/256, 256>>>(pe);
    pack_wqkv_kernel<<<(int)(((long long)LL*DD*NQKV + 255)/256), 256>>>(Wq, Wk, Wv, wqkv);
    embed_kernel<<<(int)(((long long)MT*DD + 255)/256), 256>>>(x, emb, pe, h);

    for (int l = 0; l < LL; l++) {
        // QKV projection: [8192,768] x [768,2304]
        gemm_bf16x3_kernel<<<dim3(NQKV/TN, MT/TM, 1), 256>>>(
            h, DD, 1,
            wqkv + (long long)l*DD*NQKV, NQKV, 1,
            qkv, NQKV, MT, NQKV, DD, 0);
        bias_qkv_kernel<<<(int)(((long long)MT*NQKV + 255)/256), 256>>>(qkv, bq, bk, bv, l);

        // scores = Q K^T  (batched over 192 (b,h))
        gemm_bf16x3_kernel<<<dim3(SS/TN, SS/TM, BH), 256>>>(
            qkv, NQKV, 1,
            qkv, 1, NQKV,
            scores, SS, SS, SS, DNN, 1);

        // softmax with scale + padding-mask bias
        softmax_kernel<<<BH*SS, 256>>>(scores, mask);

        // O = attn V  (batched; N=64)
        gemm_bf16x3_kernel<<<dim3(1, SS/TM, BH), 256>>>(
            scores, SS, 1,
            qkv, NQKV, 1,
            attn, DD, SS, DNN, SS, 2);

        // output projection
        gemm_bf16x3_kernel<<<dim3(DD/TN, MT/TM, 1), 256>>>(
            attn, DD, 1,
            Wo + (long long)l*DD*DD, DD, 1,
            proj, DD, MT, DD, DD, 0);
        resid_ln_kernel<<<MT, 256>>>(h, proj, bo + (long long)l*DD,
                                     g1 + (long long)l*DD, be1 + (long long)l*DD, h);

        // FFN
        gemm_bf16x3_kernel<<<dim3(FF/TN, MT/TM, 1), 256>>>(
            h, DD, 1,
            W1 + (long long)l*DD*FF, FF, 1,
            ffn, FF, MT, FF, DD, 0);
        bias_relu_kernel<<<(int)(((long long)MT*FF + 255)/256), 256>>>(ffn, b1, l);
        gemm_bf16x3_kernel<<<dim3(DD/TN, MT/TM, 1), 256>>>(
            ffn, FF, 1,
            W2 + (long long)l*FF*DD, DD, 1,
            proj, DD, MT, DD, FF, 0);

        float* hout = (l == LL-1) ? out : h;
        resid_ln_kernel<<<MT, 256>>>(h, proj, b2 + (long long)l*DD,
                                     g2 + (long long)l*DD, be2 + (long long)l*DD, hout);
    }
}

// round 15
// speedup vs baseline: 1.7434x; 1.7434x over previous
#include <cuda_runtime.h>
#include <cuda_bf16.h>
#include <mma.h>
#include <math.h>
#include <cstdint>

using namespace nvcuda;

// ---------------- problem constants ----------------
#define BB   16
#define SS   512
#define DD   768
#define HH   12
#define DNN  64
#define FF   3072
#define LL   6
#define MT   (BB*SS)        // 8192 tokens
#define NQKV (3*DD)         // 2304
#define BH   (BB*HH)        // 192
#define NEGB (-1e9f)

typedef __nv_bfloat16 bf16;

// ---------------- scratch (device globals: allocation-free rule) ----------------
__device__ float g_h[MT*DD];
__device__ bf16  g_hH[MT*DD],  g_hL[MT*DD];
__device__ bf16  g_qkvH[MT*NQKV], g_qkvL[MT*NQKV];
__device__ float g_scores[(size_t)BH*SS*SS];
__device__ bf16  g_probH[(size_t)BH*SS*SS], g_probL[(size_t)BH*SS*SS];
__device__ bf16  g_attnH[MT*DD], g_attnL[MT*DD];
__device__ float g_proj[MT*DD];
__device__ bf16  g_ffnH[MT*FF], g_ffnL[MT*FF];
__device__ bf16  g_wqkvH[(size_t)LL*DD*NQKV], g_wqkvL[(size_t)LL*DD*NQKV];
__device__ bf16  g_woH[(size_t)LL*DD*DD],     g_woL[(size_t)LL*DD*DD];
__device__ bf16  g_w1H[(size_t)LL*DD*FF],     g_w1L[(size_t)LL*DD*FF];
__device__ bf16  g_w2H[(size_t)LL*FF*DD],     g_w2L[(size_t)LL*FF*DD];
__device__ float g_bqkv[LL*NQKV];
__device__ float g_pe[SS*DD];

// ---------------- helpers ----------------
__device__ __forceinline__ void fsplit(float v, bf16& h, bf16& l){
    h = __float2bfloat16(v);
    l = __float2bfloat16(v - __bfloat162float(h));
}
__device__ __forceinline__ uint32_t smem_u32(const void* p){
    uint32_t a;
    asm("{ .reg .u64 t; cvta.to.shared.u64 t, %1; cvt.u32.u64 %0, t; }" : "=r"(a) : "l"(p));
    return a;
}
__device__ __forceinline__ void cpa16(uint32_t dst, const void* src){
    asm volatile("cp.async.cg.shared.global [%0], [%1], 16;" :: "r"(dst), "l"(src));
}
#define CP_COMMIT() asm volatile("cp.async.commit_group;" ::: "memory")
#define CP_WAIT0()  asm volatile("cp.async.wait_group 0;" ::: "memory")
#define CP_WAIT1()  asm volatile("cp.async.wait_group 1;" ::: "memory")

// =====================================================================
// bf16x3 tensor-core GEMM over pre-split hi/lo bf16 planes.
//   C[M,N] = A[M,K] * B[K,N]   (fp32 math via hh + lh + hl)
// A planes: (m,k) at A[m*sAm + k]                (K contiguous)
// B planes: row layout  (k,n) at B[k*sBrow + n]  (N contiguous)   BCOL=false
//           col layout  (k,n) at B[n*sBrow + k]  (K contiguous)   BCOL=true
// Tile 128 x NT, K-chunk 32, double-buffered cp.async pipeline, 256 threads.
// bmode: 0 plain; 1 scores Q.K^T per (b,h); 2 probs.V per (b,h)
// =====================================================================
template<int NT, bool BCOL>
__global__ void __launch_bounds__(256, 2) gemm_tc(
    const bf16* __restrict__ AH, const bf16* __restrict__ AL, int sAm,
    const bf16* __restrict__ BHp, const bf16* __restrict__ BLp, int sBrow,
    float* __restrict__ CF, bf16* __restrict__ CHp, bf16* __restrict__ CLp, int ldc,
    int K, int bmode, const float* __restrict__ bias, int relu)
{
    extern __shared__ char smem[];
    constexpr int APL    = 128*48*2;                       // bytes per A plane
    constexpr int BLDrow = NT + 16;                        // 144 / 80 (elements)
    constexpr int BPL    = BCOL ? 128*48*2 : 32*BLDrow*2;  // bytes per B plane
    constexpr int STAGE  = 2*APL + 2*BPL;
    constexpr int NJ     = NT / 64;                        // n-frag count per warp

    const int tid  = threadIdx.x;
    const int warp = tid >> 5;
    const int wr   = warp >> 2;          // 0..1 (64 rows each)
    const int wc   = warp & 3;           // 0..3
    const int colbase = wc * (NT/4);
    const int row0 = blockIdx.y * 128;
    const int col0 = blockIdx.x * NT;
    const uint32_t sb = smem_u32(smem);

    // batched offsets
    size_t coff = 0;
    {
        int z = blockIdx.z;
        if (bmode == 1) {
            int b = z / HH, hh = z - (z/HH)*HH;
            size_t ao = (size_t)b*SS*NQKV + (size_t)hh*DNN;
            size_t bo = (size_t)b*SS*NQKV + DD + (size_t)hh*DNN;
            AH += ao; AL += ao; BHp += bo; BLp += bo;
            coff = (size_t)z*SS*SS;
        } else if (bmode == 2) {
            int b = z / HH, hh = z - (z/HH)*HH;
            size_t ao = (size_t)z*SS*SS;
            size_t bo = (size_t)b*SS*NQKV + 2*DD + (size_t)hh*DNN;
            AH += ao; AL += ao; BHp += bo; BLp += bo;
            coff = (size_t)b*SS*DD + (size_t)hh*DNN;
        }
    }

    // -------- staging (cp.async, 16B chunks) --------
    auto stage = [&](int kc, int buf){
        uint32_t st = sb + buf*STAGE;
        // A tile: 128 rows x 32 k, 2 planes -> 1024 chunks, 4 per thread
        #pragma unroll
        for (int j = 0; j < 4; j++) {
            int c = tid + j*256;
            int plane = c >> 9, r = (c >> 2) & 127, ch = c & 3;
            const bf16* src = (plane ? AL : AH) + (size_t)(row0 + r)*sAm + kc*32 + ch*8;
            cpa16(st + plane*APL + r*96 + ch*16, src);
        }
        if constexpr (BCOL) {
            // B as [n][k]: 128 n-rows x 32 k, 2 planes
            #pragma unroll
            for (int j = 0; j < 4; j++) {
                int c = tid + j*256;
                int plane = c >> 9, n = (c >> 2) & 127, ch = c & 3;
                const bf16* src = (plane ? BLp : BHp) + (size_t)(col0 + n)*sBrow + kc*32 + ch*8;
                cpa16(st + 2*APL + plane*BPL + n*96 + ch*16, src);
            }
        } else if constexpr (NT == 128) {
            // B as [k][n]: 32 k-rows x 128 n, 2 planes
            #pragma unroll
            for (int j = 0; j < 4; j++) {
                int c = tid + j*256;
                int plane = c >> 9, r = (c >> 4) & 31, ch = c & 15;
                const bf16* src = (plane ? BLp : BHp) + (size_t)(kc*32 + r)*sBrow + col0 + ch*8;
                cpa16(st + 2*APL + plane*BPL + r*(BLDrow*2) + ch*16, src);
            }
        } else {
            // NT==64: 32 k-rows x 64 n, 2 planes -> 512 chunks, 2 per thread
            #pragma unroll
            for (int j = 0; j < 2; j++) {
                int c = tid + j*256;
                int plane = c >> 8, r = (c >> 3) & 31, ch = c & 7;
                const bf16* src = (plane ? BLp : BHp) + (size_t)(kc*32 + r)*sBrow + col0 + ch*8;
                cpa16(st + 2*APL + plane*BPL + r*(BLDrow*2) + ch*16, src);
            }
        }
    };

    wmma::fragment<wmma::accumulator,16,16,16,float> acc[4][NJ];
    #pragma unroll
    for (int i=0;i<4;i++)
        #pragma unroll
        for (int j=0;j<NJ;j++) wmma::fill_fragment(acc[i][j], 0.0f);

    auto compute = [&](int buf){
        const bf16* As_h = (const bf16*)(smem + buf*STAGE);
        const bf16* As_l = As_h + APL/2;
        const bf16* Bs_h = (const bf16*)(smem + buf*STAGE + 2*APL);
        const bf16* Bs_l = Bs_h + BPL/2;
        #pragma unroll
        for (int kk = 0; kk < 32; kk += 16) {
            if constexpr (BCOL) {
                wmma::fragment<wmma::matrix_b,16,16,16,bf16,wmma::col_major> fbh[NJ], fbl[NJ];
                #pragma unroll
                for (int j=0;j<NJ;j++) {
                    wmma::load_matrix_sync(fbh[j], Bs_h + (colbase + j*16)*48 + kk, 48);
                    wmma::load_matrix_sync(fbl[j], Bs_l + (colbase + j*16)*48 + kk, 48);
                }
                #pragma unroll
                for (int i=0;i<4;i++) {
                    wmma::fragment<wmma::matrix_a,16,16,16,bf16,wmma::row_major> fah, fal;
                    wmma::load_matrix_sync(fah, As_h + (wr*64 + i*16)*48 + kk, 48);
                    wmma::load_matrix_sync(fal, As_l + (wr*64 + i*16)*48 + kk, 48);
                    #pragma unroll
                    for (int j=0;j<NJ;j++) {
                        wmma::mma_sync(acc[i][j], fah, fbh[j], acc[i][j]);
                        wmma::mma_sync(acc[i][j], fal, fbh[j], acc[i][j]);
                        wmma::mma_sync(acc[i][j], fah, fbl[j], acc[i][j]);
                    }
                }
            } else {
                wmma::fragment<wmma::matrix_b,16,16,16,bf16,wmma::row_major> fbh[NJ], fbl[NJ];
                #pragma unroll
                for (int j=0;j<NJ;j++) {
                    wmma::load_matrix_sync(fbh[j], Bs_h + kk*BLDrow + colbase + j*16, BLDrow);
                    wmma::load_matrix_sync(fbl[j], Bs_l + kk*BLDrow + colbase + j*16, BLDrow);
                }
                #pragma unroll
                for (int i=0;i<4;i++) {
                    wmma::fragment<wmma::matrix_a,16,16,16,bf16,wmma::row_major> fah, fal;
                    wmma::load_matrix_sync(fah, As_h + (wr*64 + i*16)*48 + kk, 48);
                    wmma::load_matrix_sync(fal, As_l + (wr*64 + i*16)*48 + kk, 48);
                    #pragma unroll
                    for (int j=0;j<NJ;j++) {
                        wmma::mma_sync(acc[i][j], fah, fbh[j], acc[i][j]);
                        wmma::mma_sync(acc[i][j], fal, fbh[j], acc[i][j]);
                        wmma::mma_sync(acc[i][j], fah, fbl[j], acc[i][j]);
                    }
                }
            }
        }
    };

    // -------- pipelined K loop --------
    const int kch = K >> 5;
    stage(0, 0);
    CP_COMMIT();
    for (int kc = 0; kc < kch; kc++) {
        if (kc + 1 < kch) {
            stage(kc + 1, (kc + 1) & 1);
            CP_COMMIT();
            CP_WAIT1();
        } else {
            CP_WAIT0();
        }
        __syncthreads();
        compute(kc & 1);
        __syncthreads();
    }

    // -------- epilogue: acc -> smem -> bias/relu -> f32 and/or hi+lo planes --------
    {
        float* sbuf = (float*)smem;
        constexpr int EP = NT + 4;
        #pragma unroll
        for (int i=0;i<4;i++)
            #pragma unroll
            for (int j=0;j<NJ;j++)
                wmma::store_matrix_sync(&sbuf[(wr*64 + i*16)*EP + colbase + j*16],
                                        acc[i][j], EP, wmma::mem_row_major);
        __syncthreads();
        constexpr int LOGNT = (NT == 128) ? 7 : 6;
        for (int idx = tid; idx < 128*NT; idx += 256) {
            int r  = idx >> LOGNT;
            int cn = idx & (NT - 1);
            float v = sbuf[r*EP + cn];
            int gc = col0 + cn;
            if (bias) v += __ldg(bias + gc);
            if (relu) v = fmaxf(v, 0.0f);
            size_t off = coff + (size_t)(row0 + r)*ldc + gc;
            if (CF) CF[off] = v;
            if (CHp) {
                bf16 hi, lo; fsplit(v, hi, lo);
                CHp[off] = hi; CLp[off] = lo;
            }
        }
    }
}

// ================= pointwise / setup kernels =================
__global__ void pe_kernel(float* __restrict__ pe){
    int idx = blockIdx.x*256 + threadIdx.x;
    if (idx >= SS*DD) return;
    int pos = idx / DD, c = idx % DD;
    double i = (double)(c >> 1);
    float val;
    if ((c & 1) == 0) {
        double ang = (double)pos * pow(10000.0, -2.0*i/(double)DD);
        val = (float)sin(ang);
    } else {
        double ang = (double)pos * pow(10000.0, -2.0*(i+1.0)/(double)DD);
        val = (float)cos(ang);
    }
    pe[idx] = val;
}

__global__ void embed_kernel(const int* __restrict__ x, const float* __restrict__ emb,
                             const float* __restrict__ pe, float* __restrict__ h,
                             bf16* __restrict__ hH, bf16* __restrict__ hL){
    long long idx = (long long)blockIdx.x*256 + threadIdx.x;
    if (idx >= (long long)MT*DD) return;
    int m = (int)(idx / DD), c = (int)(idx % DD);
    int tok = x[m];
    float v = emb[(long long)tok*DD + c] + pe[(m & (SS-1))*DD + c];
    h[idx] = v;
    bf16 hi, lo; fsplit(v, hi, lo);
    hH[idx] = hi; hL[idx] = lo;
}

__global__ void pack_wqkv_kernel(const float* __restrict__ Wq, const float* __restrict__ Wk,
                                 const float* __restrict__ Wv,
                                 bf16* __restrict__ oH, bf16* __restrict__ oL){
    long long i = (long long)blockIdx.x*256 + threadIdx.x;
    const long long TOT = (long long)LL*DD*NQKV;
    if (i >= TOT) return;
    int n = (int)(i % NQKV);
    long long t = i / NQKV;
    int d = (int)(t % DD);
    int l = (int)(t / DD);
    int seg = n / DD, nn = n % DD;
    int hh = nn >> 6, e = nn & 63;
    const float* W = (seg==0) ? Wq : (seg==1 ? Wk : Wv);
    float v = W[(((long long)l*HH + hh)*DD + d)*DNN + e];
    bf16 hi, lo; fsplit(v, hi, lo);
    oH[i] = hi; oL[i] = lo;
}

__global__ void pack_bias_kernel(const float* __restrict__ bq, const float* __restrict__ bk,
                                 const float* __restrict__ bv, float* __restrict__ out){
    int i = blockIdx.x*256 + threadIdx.x;
    if (i >= LL*NQKV) return;
    int l = i / NQKV, n = i % NQKV;
    int seg = n / DD, m = n % DD;
    const float* bb = (seg==0) ? bq : (seg==1 ? bk : bv);
    out[i] = bb[l*DD + m];
}

__global__ void split_kernel(const float* __restrict__ src, bf16* __restrict__ dH,
                             bf16* __restrict__ dL, long long n){
    long long i = (long long)blockIdx.x*256 + threadIdx.x;
    if (i >= n) return;
    bf16 hi, lo; fsplit(src[i], hi, lo);
    dH[i] = hi; dL[i] = lo;
}

__device__ __forceinline__ float warp_sum(float v){
    #pragma unroll
    for (int o=16;o;o>>=1) v += __shfl_xor_sync(0xffffffffu, v, o);
    return v;
}
__device__ __forceinline__ float warp_max(float v){
    #pragma unroll
    for (int o=16;o;o>>=1) v = fmaxf(v, __shfl_xor_sync(0xffffffffu, v, o));
    return v;
}
__device__ __forceinline__ float block_sum8(float v, float* red){
    v = warp_sum(v);
    if ((threadIdx.x & 31) == 0) red[threadIdx.x >> 5] = v;
    __syncthreads();
    float t = red[0];
    #pragma unroll
    for (int i=1;i<8;i++) t += red[i];
    __syncthreads();
    return t;
}
__device__ __forceinline__ float block_max8(float v, float* red){
    v = warp_max(v);
    if ((threadIdx.x & 31) == 0) red[threadIdx.x >> 5] = v;
    __syncthreads();
    float t = red[0];
    #pragma unroll
    for (int i=1;i<8;i++) t = fmaxf(t, red[i]);
    __syncthreads();
    return t;
}

// scale + mask-bias + softmax; writes probs as hi/lo planes
__global__ void __launch_bounds__(256) softmax_kernel(const float* __restrict__ scores,
                                                      const int* __restrict__ mask,
                                                      bf16* __restrict__ pH,
                                                      bf16* __restrict__ pL){
    __shared__ float red[8];
    long long r = blockIdx.x;
    long long z = r >> 9;
    int s = (int)(r & (SS-1));
    int b = (int)(z / HH);
    const float* Srow = scores + r*SS;
    const int* Mrow = mask + ((long long)b*SS + s)*SS;
    int tid = threadIdx.x;
    int t0 = tid, t1 = tid + 256;
    float v0 = Srow[t0]*0.125f + (Mrow[t0] ? NEGB : 0.0f);
    float v1 = Srow[t1]*0.125f + (Mrow[t1] ? NEGB : 0.0f);
    float mx = block_max8(fmaxf(v0, v1), red);
    float e0 = expf(v0 - mx), e1 = expf(v1 - mx);
    float sum = block_sum8(e0 + e1, red);
    float inv = 1.0f / sum;
    bf16 hi, lo;
    fsplit(e0*inv, hi, lo); pH[r*SS + t0] = hi; pL[r*SS + t0] = lo;
    fsplit(e1*inv, hi, lo); pH[r*SS + t1] = hi; pL[r*SS + t1] = lo;
}

// out = LayerNorm(hin + proj + bias) * gamma + beta  (+ optional hi/lo planes)
__global__ void __launch_bounds__(256) resid_ln_kernel(
    const float* __restrict__ hin, const float* __restrict__ proj,
    const float* __restrict__ bias, const float* __restrict__ gamma,
    const float* __restrict__ beta, float* __restrict__ hout,
    bf16* __restrict__ outH, bf16* __restrict__ outL)
{
    __shared__ float red[8];
    long long row = blockIdx.x;
    int tid = threadIdx.x;
    float v[3];
    float s = 0.0f;
    #pragma unroll
    for (int t=0;t<3;t++){
        int c = tid + t*256;
        float val = hin[row*DD + c] + proj[row*DD + c] + bias[c];
        v[t] = val; s += val;
    }
    s = block_sum8(s, red);
    float mean = s * (1.0f/DD);
    float sq = 0.0f;
    #pragma unroll
    for (int t=0;t<3;t++){ float d = v[t]-mean; sq += d*d; }
    sq = block_sum8(sq, red);
    float rstd = rsqrtf(sq*(1.0f/DD) + 1e-5f);
    #pragma unroll
    for (int t=0;t<3;t++){
        int c = tid + t*256;
        float o = (v[t]-mean)*rstd*gamma[c] + beta[c];
        hout[row*DD + c] = o;
        if (outH) {
            bf16 hi, lo; fsplit(o, hi, lo);
            outH[row*DD + c] = hi; outL[row*DD + c] = lo;
        }
    }
}

// ================= host orchestration =================
// dynamic smem sizes per instantiation
#define SM_128_ROW  86016   // 2*(2*12288 + 2*32*144*2)
#define SM_128_COL  98304   // 2*(2*12288 + 2*12288)
#define SM_64_ROW   69632   // 2*(2*12288 + 2*32*80*2)

extern "C" void kernel_launch(void* const* d_in, const int* in_sizes, int n_in,
                              void* d_out, int out_size)
{
    (void)in_sizes; (void)n_in; (void)out_size;
    const int*   x    = (const int*)  d_in[0];
    const int*   mask = (const int*)  d_in[1];
    const float* emb  = (const float*)d_in[2];
    const float* Wq   = (const float*)d_in[3];
    const float* bq   = (const float*)d_in[4];
    const float* Wk   = (const float*)d_in[5];
    const float* bk   = (const float*)d_in[6];
    const float* Wv   = (const float*)d_in[7];
    const float* bv   = (const float*)d_in[8];
    const float* Wo   = (const float*)d_in[9];
    const float* bo   = (const float*)d_in[10];
    const float* W1   = (const float*)d_in[11];
    const float* b1   = (const float*)d_in[12];
    const float* W2   = (const float*)d_in[13];
    const float* b2   = (const float*)d_in[14];
    const float* g1   = (const float*)d_in[15];
    const float* be1  = (const float*)d_in[16];
    const float* g2   = (const float*)d_in[17];
    const float* be2  = (const float*)d_in[18];
    float* out = (float*)d_out;

    float *h, *scores, *proj, *bqkv, *pe;
    bf16 *hH,*hL,*qkvH,*qkvL,*probH,*probL,*attnH,*attnL,*ffnH,*ffnL;
    bf16 *wqkvH,*wqkvL,*woH,*woL,*w1H,*w1L,*w2H,*w2L;
    cudaGetSymbolAddress((void**)&h,      g_h);
    cudaGetSymbolAddress((void**)&hH,     g_hH);
    cudaGetSymbolAddress((void**)&hL,     g_hL);
    cudaGetSymbolAddress((void**)&qkvH,   g_qkvH);
    cudaGetSymbolAddress((void**)&qkvL,   g_qkvL);
    cudaGetSymbolAddress((void**)&scores, g_scores);
    cudaGetSymbolAddress((void**)&probH,  g_probH);
    cudaGetSymbolAddress((void**)&probL,  g_probL);
    cudaGetSymbolAddress((void**)&attnH,  g_attnH);
    cudaGetSymbolAddress((void**)&attnL,  g_attnL);
    cudaGetSymbolAddress((void**)&proj,   g_proj);
    cudaGetSymbolAddress((void**)&ffnH,   g_ffnH);
    cudaGetSymbolAddress((void**)&ffnL,   g_ffnL);
    cudaGetSymbolAddress((void**)&wqkvH,  g_wqkvH);
    cudaGetSymbolAddress((void**)&wqkvL,  g_wqkvL);
    cudaGetSymbolAddress((void**)&woH,    g_woH);
    cudaGetSymbolAddress((void**)&woL,    g_woL);
    cudaGetSymbolAddress((void**)&w1H,    g_w1H);
    cudaGetSymbolAddress((void**)&w1L,    g_w1L);
    cudaGetSymbolAddress((void**)&w2H,    g_w2H);
    cudaGetSymbolAddress((void**)&w2L,    g_w2L);
    cudaGetSymbolAddress((void**)&bqkv,   g_bqkv);
    cudaGetSymbolAddress((void**)&pe,     g_pe);

    static bool attr_set = false;
    if (!attr_set) {
        cudaFuncSetAttribute(gemm_tc<128,false>, cudaFuncAttributeMaxDynamicSharedMemorySize, SM_128_ROW);
        cudaFuncSetAttribute(gemm_tc<128,true >, cudaFuncAttributeMaxDynamicSharedMemorySize, SM_128_COL);
        cudaFuncSetAttribute(gemm_tc<64, false>, cudaFuncAttributeMaxDynamicSharedMemorySize, SM_64_ROW);
        attr_set = true;
    }

    // ---- setup: PE, packed weights (hi/lo planes), embeddings ----
    pe_kernel<<<(SS*DD + 255)/256, 256>>>(pe);
    pack_wqkv_kernel<<<(int)(((long long)LL*DD*NQKV + 255)/256), 256>>>(Wq, Wk, Wv, wqkvH, wqkvL);
    pack_bias_kernel<<<(LL*NQKV + 255)/256, 256>>>(bq, bk, bv, bqkv);
    {
        long long nWo = (long long)LL*DD*DD;
        long long nW1 = (long long)LL*DD*FF;
        split_kernel<<<(int)((nWo + 255)/256), 256>>>(Wo, woH, woL, nWo);
        split_kernel<<<(int)((nW1 + 255)/256), 256>>>(W1, w1H, w1L, nW1);
        split_kernel<<<(int)((nW1 + 255)/256), 256>>>(W2, w2H, w2L, nW1);
    }
    embed_kernel<<<(int)(((long long)MT*DD + 255)/256), 256>>>(x, emb, pe, h, hH, hL);

    for (int l = 0; l < LL; l++) {
        // QKV projection (+fused bias), output as hi/lo planes only
        gemm_tc<128,false><<<dim3(NQKV/128, MT/128, 1), 256, SM_128_ROW>>>(
            hH, hL, DD,
            wqkvH + (size_t)l*DD*NQKV, wqkvL + (size_t)l*DD*NQKV, NQKV,
            nullptr, qkvH, qkvL, NQKV, DD, 0, bqkv + (size_t)l*NQKV, 0);

        // scores = Q K^T (batched over 192 (b,h)), col-major B, f32 out
        gemm_tc<128,true><<<dim3(SS/128, SS/128, BH), 256, SM_128_COL>>>(
            qkvH, qkvL, NQKV,
            qkvH, qkvL, NQKV,
            scores, nullptr, nullptr, SS, DNN, 1, nullptr, 0);

        // softmax (scale + padding-mask) -> probs hi/lo planes
        softmax_kernel<<<BH*SS, 256>>>(scores, mask, probH, probL);

        // O = probs V (batched, N=64), output as hi/lo planes
        gemm_tc<64,false><<<dim3(1, SS/128, BH), 256, SM_64_ROW>>>(
            probH, probL, SS,
            qkvH, qkvL, NQKV,
            nullptr, attnH, attnL, DD, SS, 2, nullptr, 0);

        // output projection -> proj f32
        gemm_tc<128,false><<<dim3(DD/128, MT/128, 1), 256, SM_128_ROW>>>(
            attnH, attnL, DD,
            woH + (size_t)l*DD*DD, woL + (size_t)l*DD*DD, DD,
            proj, nullptr, nullptr, DD, DD, 0, nullptr, 0);
        resid_ln_kernel<<<MT, 256>>>(h, proj, bo + (size_t)l*DD,
                                     g1 + (size_t)l*DD, be1 + (size_t)l*DD,
                                     h, hH, hL);

        // FFN1 (+bias +relu) -> ffn planes
        gemm_tc<128,false><<<dim3(FF/128, MT/128, 1), 256, SM_128_ROW>>>(
            hH, hL, DD,
            w1H + (size_t)l*DD*FF, w1L + (size_t)l*DD*FF, FF,
            nullptr, ffnH, ffnL, FF, DD, 0, b1 + (size_t)l*FF, 1);
        // FFN2 -> proj f32
        gemm_tc<128,false><<<dim3(DD/128, MT/128, 1), 256, SM_128_ROW>>>(
            ffnH, ffnL, FF,
            w2H + (size_t)l*FF*DD, w2L + (size_t)l*FF*DD, DD,
            proj, nullptr, nullptr, DD, FF, 0, nullptr, 0);

        if (l == LL-1) {
            resid_ln_kernel<<<MT, 256>>>(h, proj, b2 + (size_t)l*DD,
                                         g2 + (size_t)l*DD, be2 + (size_t)l*DD,
                                         out, nullptr, nullptr);
        } else {
            resid_ln_kernel<<<MT, 256>>>(h, proj, b2 + (size_t)l*DD,
                                         g2 + (size_t)l*DD, be2 + (size_t)l*DD,
                                         h, hH, hL);
        }
    }
}

// round 16
// speedup vs baseline: 1.7865x; 1.0247x over previous
#include <cuda_runtime.h>
#include <cuda_bf16.h>
#include <mma.h>
#include <math.h>
#include <cstdint>

using namespace nvcuda;

// ---------------- problem constants ----------------
#define BB   16
#define SS   512
#define DD   768
#define HH   12
#define DNN  64
#define FF   3072
#define LL   6
#define MT   (BB*SS)        // 8192 tokens
#define NQKV (3*DD)         // 2304
#define BH   (BB*HH)        // 192
#define NEGB (-1e9f)

typedef __nv_bfloat16 bf16;

// ---------------- scratch (device globals: allocation-free rule) ----------------
__device__ float g_h[MT*DD];
__device__ bf16  g_hH[MT*DD],  g_hL[MT*DD];
__device__ bf16  g_qkvH[MT*NQKV], g_qkvL[MT*NQKV];
__device__ float g_scores[(size_t)BH*SS*SS];
__device__ bf16  g_probH[(size_t)BH*SS*SS], g_probL[(size_t)BH*SS*SS];
__device__ bf16  g_attnH[MT*DD], g_attnL[MT*DD];
__device__ float g_proj[MT*DD];
__device__ bf16  g_ffnH[MT*FF], g_ffnL[MT*FF];
__device__ bf16  g_wqkvH[(size_t)LL*DD*NQKV], g_wqkvL[(size_t)LL*DD*NQKV];
__device__ bf16  g_woH[(size_t)LL*DD*DD],     g_woL[(size_t)LL*DD*DD];
__device__ bf16  g_w1H[(size_t)LL*DD*FF],     g_w1L[(size_t)LL*DD*FF];
__device__ bf16  g_w2H[(size_t)LL*FF*DD],     g_w2L[(size_t)LL*FF*DD];
__device__ float g_bqkv[LL*NQKV];
__device__ float g_pe[SS*DD];

// ---------------- helpers ----------------
__device__ __forceinline__ void fsplit(float v, bf16& h, bf16& l){
    h = __float2bfloat16(v);
    l = __float2bfloat16(v - __bfloat162float(h));
}
__device__ __forceinline__ uint32_t smem_u32(const void* p){
    uint32_t a;
    asm("{ .reg .u64 t; cvta.to.shared.u64 t, %1; cvt.u32.u64 %0, t; }" : "=r"(a) : "l"(p));
    return a;
}
__device__ __forceinline__ void cpa16(uint32_t dst, const void* src){
    asm volatile("cp.async.cg.shared.global [%0], [%1], 16;" :: "r"(dst), "l"(src));
}
#define CP_COMMIT() asm volatile("cp.async.commit_group;" ::: "memory")
#define CP_WAIT0()  asm volatile("cp.async.wait_group 0;" ::: "memory")
#define CP_WAIT1()  asm volatile("cp.async.wait_group 1;" ::: "memory")

// =====================================================================
// bf16x3 tensor-core GEMM over pre-split hi/lo bf16 planes.
//   C[M,N] = A[M,K] * B[K,N]   (fp32 math via hh + lh + hl)
// A planes: (m,k) at A[m*sAm + k]                (K contiguous)
// B planes: row layout  (k,n) at B[k*sBrow + n]  (N contiguous)   BCOL=false
//           col layout  (k,n) at B[n*sBrow + k]  (K contiguous)   BCOL=true
// Tile 128 x NT, 4 warps (each 64 x NT/2), K-chunk 32, double-buffered
// cp.async pipeline, 128 threads, 2 CTAs/SM.
// bmode: 0 plain; 1 scores Q.K^T per (b,h); 2 probs.V per (b,h)
// =====================================================================
template<int NT, bool BCOL>
__global__ void __launch_bounds__(128, 2) gemm_tc(
    const bf16* __restrict__ AH, const bf16* __restrict__ AL, int sAm,
    const bf16* __restrict__ BHp, const bf16* __restrict__ BLp, int sBrow,
    float* __restrict__ CF, bf16* __restrict__ CHp, bf16* __restrict__ CLp, int ldc,
    int K, int bmode, const float* __restrict__ bias, int relu)
{
    extern __shared__ char smem[];
    constexpr int APL    = 128*48*2;                       // bytes per A plane
    constexpr int BLDrow = NT + 16;                        // 144 / 80 (elements)
    constexpr int BPL    = BCOL ? 128*48*2 : 32*BLDrow*2;  // bytes per B plane
    constexpr int STAGE  = 2*APL + 2*BPL;
    constexpr int NJ     = NT / 32;                        // n-frags per warp (4 or 2)

    const int tid  = threadIdx.x;
    const int warp = tid >> 5;
    const int wr   = warp >> 1;          // 0..1 (64 rows each)
    const int wc   = warp & 1;           // 0..1
    const int colbase = wc * (NT/2);
    const int row0 = blockIdx.y * 128;
    const int col0 = blockIdx.x * NT;
    const uint32_t sb = smem_u32(smem);

    // batched offsets
    size_t coff = 0;
    {
        int z = blockIdx.z;
        if (bmode == 1) {
            int b = z / HH, hh = z - (z/HH)*HH;
            size_t ao = (size_t)b*SS*NQKV + (size_t)hh*DNN;
            size_t bo = (size_t)b*SS*NQKV + DD + (size_t)hh*DNN;
            AH += ao; AL += ao; BHp += bo; BLp += bo;
            coff = (size_t)z*SS*SS;
        } else if (bmode == 2) {
            int b = z / HH, hh = z - (z/HH)*HH;
            size_t ao = (size_t)z*SS*SS;
            size_t bo = (size_t)b*SS*NQKV + 2*DD + (size_t)hh*DNN;
            AH += ao; AL += ao; BHp += bo; BLp += bo;
            coff = (size_t)b*SS*DD + (size_t)hh*DNN;
        }
    }

    // -------- staging (cp.async, 16B chunks), 128 threads --------
    auto stage = [&](int kc, int buf){
        uint32_t st = sb + buf*STAGE;
        // A tile: 128 rows x 32 k, 2 planes -> 1024 chunks, 8 per thread
        #pragma unroll
        for (int j = 0; j < 8; j++) {
            int c = tid + j*128;
            int plane = c >> 9, r = (c >> 2) & 127, ch = c & 3;
            const bf16* src = (plane ? AL : AH) + (size_t)(row0 + r)*sAm + kc*32 + ch*8;
            cpa16(st + plane*APL + r*96 + ch*16, src);
        }
        if constexpr (BCOL) {
            // B as [n][k]: 128 n-rows x 32 k, 2 planes -> 1024 chunks
            #pragma unroll
            for (int j = 0; j < 8; j++) {
                int c = tid + j*128;
                int plane = c >> 9, n = (c >> 2) & 127, ch = c & 3;
                const bf16* src = (plane ? BLp : BHp) + (size_t)(col0 + n)*sBrow + kc*32 + ch*8;
                cpa16(st + 2*APL + plane*BPL + n*96 + ch*16, src);
            }
        } else if constexpr (NT == 128) {
            // B as [k][n]: 32 k-rows x 128 n, 2 planes -> 1024 chunks
            #pragma unroll
            for (int j = 0; j < 8; j++) {
                int c = tid + j*128;
                int plane = c >> 9, r = (c >> 4) & 31, ch = c & 15;
                const bf16* src = (plane ? BLp : BHp) + (size_t)(kc*32 + r)*sBrow + col0 + ch*8;
                cpa16(st + 2*APL + plane*BPL + r*(BLDrow*2) + ch*16, src);
            }
        } else {
            // NT==64: 32 k-rows x 64 n, 2 planes -> 512 chunks, 4 per thread
            #pragma unroll
            for (int j = 0; j < 4; j++) {
                int c = tid + j*128;
                int plane = c >> 8, r = (c >> 3) & 31, ch = c & 7;
                const bf16* src = (plane ? BLp : BHp) + (size_t)(kc*32 + r)*sBrow + col0 + ch*8;
                cpa16(st + 2*APL + plane*BPL + r*(BLDrow*2) + ch*16, src);
            }
        }
    };

    wmma::fragment<wmma::accumulator,16,16,16,float> acc[4][NJ];
    #pragma unroll
    for (int i=0;i<4;i++)
        #pragma unroll
        for (int j=0;j<NJ;j++) wmma::fill_fragment(acc[i][j], 0.0f);

    auto compute = [&](int buf){
        const bf16* As_h = (const bf16*)(smem + buf*STAGE);
        const bf16* As_l = As_h + APL/2;
        const bf16* Bs_h = (const bf16*)(smem + buf*STAGE + 2*APL);
        const bf16* Bs_l = Bs_h + BPL/2;
        #pragma unroll
        for (int kk = 0; kk < 32; kk += 16) {
            if constexpr (BCOL) {
                wmma::fragment<wmma::matrix_b,16,16,16,bf16,wmma::col_major> fbh[NJ], fbl[NJ];
                #pragma unroll
                for (int j=0;j<NJ;j++) {
                    wmma::load_matrix_sync(fbh[j], Bs_h + (colbase + j*16)*48 + kk, 48);
                    wmma::load_matrix_sync(fbl[j], Bs_l + (colbase + j*16)*48 + kk, 48);
                }
                #pragma unroll
                for (int i=0;i<4;i++) {
                    wmma::fragment<wmma::matrix_a,16,16,16,bf16,wmma::row_major> fah, fal;
                    wmma::load_matrix_sync(fah, As_h + (wr*64 + i*16)*48 + kk, 48);
                    wmma::load_matrix_sync(fal, As_l + (wr*64 + i*16)*48 + kk, 48);
                    #pragma unroll
                    for (int j=0;j<NJ;j++) {
                        wmma::mma_sync(acc[i][j], fah, fbh[j], acc[i][j]);
                        wmma::mma_sync(acc[i][j], fal, fbh[j], acc[i][j]);
                        wmma::mma_sync(acc[i][j], fah, fbl[j], acc[i][j]);
                    }
                }
            } else {
                wmma::fragment<wmma::matrix_b,16,16,16,bf16,wmma::row_major> fbh[NJ], fbl[NJ];
                #pragma unroll
                for (int j=0;j<NJ;j++) {
                    wmma::load_matrix_sync(fbh[j], Bs_h + kk*BLDrow + colbase + j*16, BLDrow);
                    wmma::load_matrix_sync(fbl[j], Bs_l + kk*BLDrow + colbase + j*16, BLDrow);
                }
                #pragma unroll
                for (int i=0;i<4;i++) {
                    wmma::fragment<wmma::matrix_a,16,16,16,bf16,wmma::row_major> fah, fal;
                    wmma::load_matrix_sync(fah, As_h + (wr*64 + i*16)*48 + kk, 48);
                    wmma::load_matrix_sync(fal, As_l + (wr*64 + i*16)*48 + kk, 48);
                    #pragma unroll
                    for (int j=0;j<NJ;j++) {
                        wmma::mma_sync(acc[i][j], fah, fbh[j], acc[i][j]);
                        wmma::mma_sync(acc[i][j], fal, fbh[j], acc[i][j]);
                        wmma::mma_sync(acc[i][j], fah, fbl[j], acc[i][j]);
                    }
                }
            }
        }
    };

    // -------- pipelined K loop --------
    const int kch = K >> 5;
    stage(0, 0);
    CP_COMMIT();
    for (int kc = 0; kc < kch; kc++) {
        if (kc + 1 < kch) {
            stage(kc + 1, (kc + 1) & 1);
            CP_COMMIT();
            CP_WAIT1();
        } else {
            CP_WAIT0();
        }
        __syncthreads();
        compute(kc & 1);
        __syncthreads();
    }

    // -------- epilogue: acc -> smem -> bias/relu -> f32 and/or hi+lo planes --------
    {
        float* sbuf = (float*)smem;
        constexpr int EP = NT + 4;
        #pragma unroll
        for (int i=0;i<4;i++)
            #pragma unroll
            for (int j=0;j<NJ;j++)
                wmma::store_matrix_sync(&sbuf[(wr*64 + i*16)*EP + colbase + j*16],
                                        acc[i][j], EP, wmma::mem_row_major);
        __syncthreads();
        constexpr int LOGNT = (NT == 128) ? 7 : 6;
        for (int idx = tid; idx < 128*NT; idx += 128) {
            int r  = idx >> LOGNT;
            int cn = idx & (NT - 1);
            float v = sbuf[r*EP + cn];
            int gc = col0 + cn;
            if (bias) v += __ldg(bias + gc);
            if (relu) v = fmaxf(v, 0.0f);
            size_t off = coff + (size_t)(row0 + r)*ldc + gc;
            if (CF) CF[off] = v;
            if (CHp) {
                bf16 hi, lo; fsplit(v, hi, lo);
                CHp[off] = hi; CLp[off] = lo;
            }
        }
    }
}

// ================= pointwise / setup kernels =================
__global__ void pe_kernel(float* __restrict__ pe){
    int idx = blockIdx.x*256 + threadIdx.x;
    if (idx >= SS*DD) return;
    int pos = idx / DD, c = idx % DD;
    double i = (double)(c >> 1);
    float val;
    if ((c & 1) == 0) {
        double ang = (double)pos * pow(10000.0, -2.0*i/(double)DD);
        val = (float)sin(ang);
    } else {
        double ang = (double)pos * pow(10000.0, -2.0*(i+1.0)/(double)DD);
        val = (float)cos(ang);
    }
    pe[idx] = val;
}

__global__ void embed_kernel(const int* __restrict__ x, const float* __restrict__ emb,
                             const float* __restrict__ pe, float* __restrict__ h,
                             bf16* __restrict__ hH, bf16* __restrict__ hL){
    long long idx = (long long)blockIdx.x*256 + threadIdx.x;
    if (idx >= (long long)MT*DD) return;
    int m = (int)(idx / DD), c = (int)(idx % DD);
    int tok = x[m];
    float v = emb[(long long)tok*DD + c] + pe[(m & (SS-1))*DD + c];
    h[idx] = v;
    bf16 hi, lo; fsplit(v, hi, lo);
    hH[idx] = hi; hL[idx] = lo;
}

__global__ void pack_wqkv_kernel(const float* __restrict__ Wq, const float* __restrict__ Wk,
                                 const float* __restrict__ Wv,
                                 bf16* __restrict__ oH, bf16* __restrict__ oL){
    long long i = (long long)blockIdx.x*256 + threadIdx.x;
    const long long TOT = (long long)LL*DD*NQKV;
    if (i >= TOT) return;
    int n = (int)(i % NQKV);
    long long t = i / NQKV;
    int d = (int)(t % DD);
    int l = (int)(t / DD);
    int seg = n / DD, nn = n % DD;
    int hh = nn >> 6, e = nn & 63;
    const float* W = (seg==0) ? Wq : (seg==1 ? Wk : Wv);
    float v = W[(((long long)l*HH + hh)*DD + d)*DNN + e];
    bf16 hi, lo; fsplit(v, hi, lo);
    oH[i] = hi; oL[i] = lo;
}

__global__ void pack_bias_kernel(const float* __restrict__ bq, const float* __restrict__ bk,
                                 const float* __restrict__ bv, float* __restrict__ out){
    int i = blockIdx.x*256 + threadIdx.x;
    if (i >= LL*NQKV) return;
    int l = i / NQKV, n = i % NQKV;
    int seg = n / DD, m = n % DD;
    const float* bb = (seg==0) ? bq : (seg==1 ? bk : bv);
    out[i] = bb[l*DD + m];
}

__global__ void split_kernel(const float* __restrict__ src, bf16* __restrict__ dH,
                             bf16* __restrict__ dL, long long n){
    long long i = (long long)blockIdx.x*256 + threadIdx.x;
    if (i >= n) return;
    bf16 hi, lo; fsplit(src[i], hi, lo);
    dH[i] = hi; dL[i] = lo;
}

__device__ __forceinline__ float warp_sum(float v){
    #pragma unroll
    for (int o=16;o;o>>=1) v += __shfl_xor_sync(0xffffffffu, v, o);
    return v;
}
__device__ __forceinline__ float warp_max(float v){
    #pragma unroll
    for (int o=16;o;o>>=1) v = fmaxf(v, __shfl_xor_sync(0xffffffffu, v, o));
    return v;
}
__device__ __forceinline__ float block_sum8(float v, float* red){
    v = warp_sum(v);
    if ((threadIdx.x & 31) == 0) red[threadIdx.x >> 5] = v;
    __syncthreads();
    float t = red[0];
    #pragma unroll
    for (int i=1;i<8;i++) t += red[i];
    __syncthreads();
    return t;
}
__device__ __forceinline__ float block_max8(float v, float* red){
    v = warp_max(v);
    if ((threadIdx.x & 31) == 0) red[threadIdx.x >> 5] = v;
    __syncthreads();
    float t = red[0];
    #pragma unroll
    for (int i=1;i<8;i++) t = fmaxf(t, red[i]);
    __syncthreads();
    return t;
}

// scale + mask-bias + softmax; writes probs as hi/lo planes
__global__ void __launch_bounds__(256) softmax_kernel(const float* __restrict__ scores,
                                                      const int* __restrict__ mask,
                                                      bf16* __restrict__ pH,
                                                      bf16* __restrict__ pL){
    __shared__ float red[8];
    long long r = blockIdx.x;
    long long z = r >> 9;
    int s = (int)(r & (SS-1));
    int b = (int)(z / HH);
    const float* Srow = scores + r*SS;
    const int* Mrow = mask + ((long long)b*SS + s)*SS;
    int tid = threadIdx.x;
    int t0 = tid, t1 = tid + 256;
    float v0 = Srow[t0]*0.125f + (Mrow[t0] ? NEGB : 0.0f);
    float v1 = Srow[t1]*0.125f + (Mrow[t1] ? NEGB : 0.0f);
    float mx = block_max8(fmaxf(v0, v1), red);
    float e0 = expf(v0 - mx), e1 = expf(v1 - mx);
    float sum = block_sum8(e0 + e1, red);
    float inv = 1.0f / sum;
    bf16 hi, lo;
    fsplit(e0*inv, hi, lo); pH[r*SS + t0] = hi; pL[r*SS + t0] = lo;
    fsplit(e1*inv, hi, lo); pH[r*SS + t1] = hi; pL[r*SS + t1] = lo;
}

// out = LayerNorm(hin + proj + bias) * gamma + beta  (+ optional hi/lo planes)
__global__ void __launch_bounds__(256) resid_ln_kernel(
    const float* __restrict__ hin, const float* __restrict__ proj,
    const float* __restrict__ bias, const float* __restrict__ gamma,
    const float* __restrict__ beta, float* __restrict__ hout,
    bf16* __restrict__ outH, bf16* __restrict__ outL)
{
    __shared__ float red[8];
    long long row = blockIdx.x;
    int tid = threadIdx.x;
    float v[3];
    float s = 0.0f;
    #pragma unroll
    for (int t=0;t<3;t++){
        int c = tid + t*256;
        float val = hin[row*DD + c] + proj[row*DD + c] + bias[c];
        v[t] = val; s += val;
    }
    s = block_sum8(s, red);
    float mean = s * (1.0f/DD);
    float sq = 0.0f;
    #pragma unroll
    for (int t=0;t<3;t++){ float d = v[t]-mean; sq += d*d; }
    sq = block_sum8(sq, red);
    float rstd = rsqrtf(sq*(1.0f/DD) + 1e-5f);
    #pragma unroll
    for (int t=0;t<3;t++){
        int c = tid + t*256;
        float o = (v[t]-mean)*rstd*gamma[c] + beta[c];
        hout[row*DD + c] = o;
        if (outH) {
            bf16 hi, lo; fsplit(o, hi, lo);
            outH[row*DD + c] = hi; outL[row*DD + c] = lo;
        }
    }
}

// ================= host orchestration =================
// dynamic smem sizes per instantiation
#define SM_128_ROW  86016   // 2*(2*12288 + 2*32*144*2)
#define SM_128_COL  98304   // 2*(2*12288 + 2*12288)
#define SM_64_ROW   69632   // 2*(2*12288 + 2*32*80*2)

extern "C" void kernel_launch(void* const* d_in, const int* in_sizes, int n_in,
                              void* d_out, int out_size)
{
    (void)in_sizes; (void)n_in; (void)out_size;
    const int*   x    = (const int*)  d_in[0];
    const int*   mask = (const int*)  d_in[1];
    const float* emb  = (const float*)d_in[2];
    const float* Wq   = (const float*)d_in[3];
    const float* bq   = (const float*)d_in[4];
    const float* Wk   = (const float*)d_in[5];
    const float* bk   = (const float*)d_in[6];
    const float* Wv   = (const float*)d_in[7];
    const float* bv   = (const float*)d_in[8];
    const float* Wo   = (const float*)d_in[9];
    const float* bo   = (const float*)d_in[10];
    const float* W1   = (const float*)d_in[11];
    const float* b1   = (const float*)d_in[12];
    const float* W2   = (const float*)d_in[13];
    const float* b2   = (const float*)d_in[14];
    const float* g1   = (const float*)d_in[15];
    const float* be1  = (const float*)d_in[16];
    const float* g2   = (const float*)d_in[17];
    const float* be2  = (const float*)d_in[18];
    float* out = (float*)d_out;

    float *h, *scores, *proj, *bqkv, *pe;
    bf16 *hH,*hL,*qkvH,*qkvL,*probH,*probL,*attnH,*attnL,*ffnH,*ffnL;
    bf16 *wqkvH,*wqkvL,*woH,*woL,*w1H,*w1L,*w2H,*w2L;
    cudaGetSymbolAddress((void**)&h,      g_h);
    cudaGetSymbolAddress((void**)&hH,     g_hH);
    cudaGetSymbolAddress((void**)&hL,     g_hL);
    cudaGetSymbolAddress((void**)&qkvH,   g_qkvH);
    cudaGetSymbolAddress((void**)&qkvL,   g_qkvL);
    cudaGetSymbolAddress((void**)&scores, g_scores);
    cudaGetSymbolAddress((void**)&probH,  g_probH);
    cudaGetSymbolAddress((void**)&probL,  g_probL);
    cudaGetSymbolAddress((void**)&attnH,  g_attnH);
    cudaGetSymbolAddress((void**)&attnL,  g_attnL);
    cudaGetSymbolAddress((void**)&proj,   g_proj);
    cudaGetSymbolAddress((void**)&ffnH,   g_ffnH);
    cudaGetSymbolAddress((void**)&ffnL,   g_ffnL);
    cudaGetSymbolAddress((void**)&wqkvH,  g_wqkvH);
    cudaGetSymbolAddress((void**)&wqkvL,  g_wqkvL);
    cudaGetSymbolAddress((void**)&woH,    g_woH);
    cudaGetSymbolAddress((void**)&woL,    g_woL);
    cudaGetSymbolAddress((void**)&w1H,    g_w1H);
    cudaGetSymbolAddress((void**)&w1L,    g_w1L);
    cudaGetSymbolAddress((void**)&w2H,    g_w2H);
    cudaGetSymbolAddress((void**)&w2L,    g_w2L);
    cudaGetSymbolAddress((void**)&bqkv,   g_bqkv);
    cudaGetSymbolAddress((void**)&pe,     g_pe);

    static bool attr_set = false;
    if (!attr_set) {
        cudaFuncSetAttribute(gemm_tc<128,false>, cudaFuncAttributeMaxDynamicSharedMemorySize, SM_128_ROW);
        cudaFuncSetAttribute(gemm_tc<128,true >, cudaFuncAttributeMaxDynamicSharedMemorySize, SM_128_COL);
        cudaFuncSetAttribute(gemm_tc<64, false>, cudaFuncAttributeMaxDynamicSharedMemorySize, SM_64_ROW);
        attr_set = true;
    }

    // ---- setup: PE, packed weights (hi/lo planes), embeddings ----
    pe_kernel<<<(SS*DD + 255)/256, 256>>>(pe);
    pack_wqkv_kernel<<<(int)(((long long)LL*DD*NQKV + 255)/256), 256>>>(Wq, Wk, Wv, wqkvH, wqkvL);
    pack_bias_kernel<<<(LL*NQKV + 255)/256, 256>>>(bq, bk, bv, bqkv);
    {
        long long nWo = (long long)LL*DD*DD;
        long long nW1 = (long long)LL*DD*FF;
        split_kernel<<<(int)((nWo + 255)/256), 256>>>(Wo, woH, woL, nWo);
        split_kernel<<<(int)((nW1 + 255)/256), 256>>>(W1, w1H, w1L, nW1);
        split_kernel<<<(int)((nW1 + 255)/256), 256>>>(W2, w2H, w2L, nW1);
    }
    embed_kernel<<<(int)(((long long)MT*DD + 255)/256), 256>>>(x, emb, pe, h, hH, hL);

    for (int l = 0; l < LL; l++) {
        // QKV projection (+fused bias), output as hi/lo planes only
        gemm_tc<128,false><<<dim3(NQKV/128, MT/128, 1), 128, SM_128_ROW>>>(
            hH, hL, DD,
            wqkvH + (size_t)l*DD*NQKV, wqkvL + (size_t)l*DD*NQKV, NQKV,
            nullptr, qkvH, qkvL, NQKV, DD, 0, bqkv + (size_t)l*NQKV, 0);

        // scores = Q K^T (batched over 192 (b,h)), col-major B, f32 out
        gemm_tc<128,true><<<dim3(SS/128, SS/128, BH), 128, SM_128_COL>>>(
            qkvH, qkvL, NQKV,
            qkvH, qkvL, NQKV,
            scores, nullptr, nullptr, SS, DNN, 1, nullptr, 0);

        // softmax (scale + padding-mask) -> probs hi/lo planes
        softmax_kernel<<<BH*SS, 256>>>(scores, mask, probH, probL);

        // O = probs V (batched, N=64), output as hi/lo planes
        gemm_tc<64,false><<<dim3(1, SS/128, BH), 128, SM_64_ROW>>>(
            probH, probL, SS,
            qkvH, qkvL, NQKV,
            nullptr, attnH, attnL, DD, SS, 2, nullptr, 0);

        // output projection -> proj f32
        gemm_tc<128,false><<<dim3(DD/128, MT/128, 1), 128, SM_128_ROW>>>(
            attnH, attnL, DD,
            woH + (size_t)l*DD*DD, woL + (size_t)l*DD*DD, DD,
            proj, nullptr, nullptr, DD, DD, 0, nullptr, 0);
        resid_ln_kernel<<<MT, 256>>>(h, proj, bo + (size_t)l*DD,
                                     g1 + (size_t)l*DD, be1 + (size_t)l*DD,
                                     h, hH, hL);

        // FFN1 (+bias +relu) -> ffn planes
        gemm_tc<128,false><<<dim3(FF/128, MT/128, 1), 128, SM_128_ROW>>>(
            hH, hL, DD,
            w1H + (size_t)l*DD*FF, w1L + (size_t)l*DD*FF, FF,
            nullptr, ffnH, ffnL, FF, DD, 0, b1 + (size_t)l*FF, 1);
        // FFN2 -> proj f32
        gemm_tc<128,false><<<dim3(DD/128, MT/128, 1), 128, SM_128_ROW>>>(
            ffnH, ffnL, FF,
            w2H + (size_t)l*FF*DD, w2L + (size_t)l*FF*DD, DD,
            proj, nullptr, nullptr, DD, FF, 0, nullptr, 0);

        if (l == LL-1) {
            resid_ln_kernel<<<MT, 256>>>(h, proj, b2 + (size_t)l*DD,
                                         g2 + (size_t)l*DD, be2 + (size_t)l*DD,
                                         out, nullptr, nullptr);
        } else {
            resid_ln_kernel<<<MT, 256>>>(h, proj, b2 + (size_t)l*DD,
                                         g2 + (size_t)l*DD, be2 + (size_t)l*DD,
                                         h, hH, hL);
        }
    }
}